// round 1
// baseline (speedup 1.0000x reference)
#include <cuda_runtime.h>

#define B_   8
#define N_   1024
#define H_   768
#define NH_  12
#define HD_  64
#define E_   131072
#define NSEG 8192   // B_*N_

// ---------------- device scratch (no allocations allowed) ----------------
__device__ float g_q[NSEG * H_];
__device__ float g_k[NSEG * H_];
__device__ float g_v[NSEG * H_];
__device__ int   g_counts[NSEG];
__device__ int   g_offsets[NSEG + 1];
__device__ int   g_cursor[NSEG];
__device__ int   g_rowj[E_];

// ---------------- QKV projection: tiled fp32 GEMM ----------------
// C(z) = A(8192x768) @ W(z)(768x768), z in {q,k,v} via blockIdx.z
__global__ __launch_bounds__(256, 2)
void gemm_qkv(const float* __restrict__ A, const float* __restrict__ Wq,
              const float* __restrict__ Wk, const float* __restrict__ Wv)
{
    constexpr int BM = 128, BN = 128, BK = 16;
    __shared__ float As[BK][BM];
    __shared__ float Bs[BK][BN];

    const float* W = (blockIdx.z == 0) ? Wq : (blockIdx.z == 1) ? Wk : Wv;
    float* C = (blockIdx.z == 0) ? g_q : (blockIdx.z == 1) ? g_k : g_v;

    const int bm = blockIdx.x * BM;
    const int bn = blockIdx.y * BN;
    const int tid = threadIdx.x;
    const int tx = tid & 15;
    const int ty = tid >> 4;

    // global->shared load mapping
    const int arow = tid >> 2;          // 0..63
    const int ac   = (tid & 3) * 4;     // 0..12 (float4 col within BK)
    const int brow = tid >> 5;          // 0..7
    const int bc   = (tid & 31) * 4;    // 0..124 (float4 col within BN)

    float acc[8][8];
    #pragma unroll
    for (int i = 0; i < 8; i++)
        #pragma unroll
        for (int j = 0; j < 8; j++) acc[i][j] = 0.f;

    for (int k0 = 0; k0 < H_; k0 += BK) {
        float4 a0 = *(const float4*)(A + (size_t)(bm + arow)      * H_ + k0 + ac);
        float4 a1 = *(const float4*)(A + (size_t)(bm + arow + 64) * H_ + k0 + ac);
        float4 b0 = *(const float4*)(W + (size_t)(k0 + brow)     * H_ + bn + bc);
        float4 b1 = *(const float4*)(W + (size_t)(k0 + brow + 8) * H_ + bn + bc);
        __syncthreads();   // previous tile's compute done
        As[ac + 0][arow] = a0.x; As[ac + 1][arow] = a0.y;
        As[ac + 2][arow] = a0.z; As[ac + 3][arow] = a0.w;
        As[ac + 0][arow + 64] = a1.x; As[ac + 1][arow + 64] = a1.y;
        As[ac + 2][arow + 64] = a1.z; As[ac + 3][arow + 64] = a1.w;
        *(float4*)&Bs[brow][bc]     = b0;
        *(float4*)&Bs[brow + 8][bc] = b1;
        __syncthreads();
        #pragma unroll
        for (int k = 0; k < BK; k++) {
            float4 ra0 = *(const float4*)&As[k][ty * 8];
            float4 ra1 = *(const float4*)&As[k][ty * 8 + 4];
            float4 rb0 = *(const float4*)&Bs[k][tx * 8];
            float4 rb1 = *(const float4*)&Bs[k][tx * 8 + 4];
            float ra[8] = {ra0.x, ra0.y, ra0.z, ra0.w, ra1.x, ra1.y, ra1.z, ra1.w};
            float rb[8] = {rb0.x, rb0.y, rb0.z, rb0.w, rb1.x, rb1.y, rb1.z, rb1.w};
            #pragma unroll
            for (int i = 0; i < 8; i++)
                #pragma unroll
                for (int j = 0; j < 8; j++)
                    acc[i][j] = fmaf(ra[i], rb[j], acc[i][j]);
        }
    }
    #pragma unroll
    for (int i = 0; i < 8; i++) {
        float4 o0 = {acc[i][0], acc[i][1], acc[i][2], acc[i][3]};
        float4 o1 = {acc[i][4], acc[i][5], acc[i][6], acc[i][7]};
        float* cp = C + (size_t)(bm + ty * 8 + i) * H_ + bn + tx * 8;
        *(float4*)cp       = o0;
        *(float4*)(cp + 4) = o1;
    }
}

// ---------------- edge bucketing: counts -> scan -> scatter ----------------
__global__ void zero_counts_kernel() {
    int i = blockIdx.x * blockDim.x + threadIdx.x;
    if (i < NSEG) g_counts[i] = 0;
}

__global__ void hist_kernel(const int* __restrict__ ei) {
    int e = blockIdx.x * blockDim.x + threadIdx.x;
    if (e < E_) {
        int seg = ei[e] * N_ + ei[E_ + e];   // b*N + i
        atomicAdd(&g_counts[seg], 1);
    }
}

__global__ __launch_bounds__(1024)
void scan_kernel() {
    __shared__ int sums[1024];
    int tid = threadIdx.x;
    int base = tid * 8;
    int c[8];
    int tot = 0;
    #pragma unroll
    for (int i = 0; i < 8; i++) { c[i] = g_counts[base + i]; tot += c[i]; }
    sums[tid] = tot;
    __syncthreads();
    for (int off = 1; off < 1024; off <<= 1) {
        int v = (tid >= off) ? sums[tid - off] : 0;
        __syncthreads();
        sums[tid] += v;
        __syncthreads();
    }
    int run = sums[tid] - tot;  // exclusive prefix for this thread's chunk
    #pragma unroll
    for (int i = 0; i < 8; i++) {
        g_offsets[base + i] = run;
        g_cursor[base + i]  = run;
        run += c[i];
    }
    if (tid == 1023) g_offsets[NSEG] = run;
}

__global__ void scatter_kernel(const int* __restrict__ ei) {
    int e = blockIdx.x * blockDim.x + threadIdx.x;
    if (e < E_) {
        int b   = ei[e];
        int seg = b * N_ + ei[E_ + e];
        int pos = atomicAdd(&g_cursor[seg], 1);
        g_rowj[pos] = b * N_ + ei[2 * E_ + e];   // tail-node row index
    }
}

// ---------------- attention: one warp per segment, online softmax ----------------
__global__ __launch_bounds__(128)
void attn_kernel(float* __restrict__ out) {
    int wglobal = (blockIdx.x * blockDim.x + threadIdx.x) >> 5;
    if (wglobal >= NSEG) return;
    int lane = threadIdx.x & 31;

    const float* qrow = g_q + (size_t)wglobal * H_;
    float qr[24];
    #pragma unroll
    for (int t = 0; t < 24; t++) qr[t] = qrow[lane + 32 * t];

    float m[12], r[12], acc[24];
    #pragma unroll
    for (int h = 0; h < 12; h++) { m[h] = -1e30f; r[h] = 0.f; }
    #pragma unroll
    for (int t = 0; t < 24; t++) acc[t] = 0.f;

    int p0 = g_offsets[wglobal];
    int p1 = g_offsets[wglobal + 1];
    for (int p = p0; p < p1; p++) {
        int rowj = g_rowj[p];
        const float* krow = g_k + (size_t)rowj * H_;
        const float* vrow = g_v + (size_t)rowj * H_;

        // per-head partial dot: head h owns elements [64h, 64h+64)
        float part[12];
        #pragma unroll
        for (int h = 0; h < 12; h++) {
            part[h] = qr[2 * h]     * krow[lane + 64 * h]
                    + qr[2 * h + 1] * krow[lane + 64 * h + 32];
        }
        // warp all-reduce of 12 per-head partials
        #pragma unroll
        for (int off = 16; off > 0; off >>= 1)
            #pragma unroll
            for (int h = 0; h < 12; h++)
                part[h] += __shfl_xor_sync(0xffffffffu, part[h], off);

        float vr[24];
        #pragma unroll
        for (int t = 0; t < 24; t++) vr[t] = vrow[lane + 32 * t];

        // online softmax update (identical across lanes; warp-uniform)
        #pragma unroll
        for (int h = 0; h < 12; h++) {
            float sc = part[h] * 0.125f;     // 1/sqrt(64)
            float mn = fmaxf(m[h], sc);
            float f  = __expf(m[h] - mn);
            float w  = __expf(sc - mn);
            r[h] = r[h] * f + w;
            m[h] = mn;
            acc[2 * h]     = acc[2 * h]     * f + w * vr[2 * h];
            acc[2 * h + 1] = acc[2 * h + 1] * f + w * vr[2 * h + 1];
        }
    }

    float inv[12];
    #pragma unroll
    for (int h = 0; h < 12; h++) inv[h] = 1.f / fmaxf(r[h], 1e-9f);
    float* orow = out + (size_t)wglobal * H_;
    #pragma unroll
    for (int t = 0; t < 24; t++) orow[lane + 32 * t] = acc[t] * inv[t >> 1];
}

// ---------------- launch ----------------
extern "C" void kernel_launch(void* const* d_in, const int* in_sizes, int n_in,
                              void* d_out, int out_size) {
    const float* x  = (const float*)d_in[0];   // node_states (B,N,H)
    const int*   ei = (const int*)  d_in[1];   // edge_indices (4,E)
    const float* Wq = (const float*)d_in[2];
    const float* Wk = (const float*)d_in[3];
    const float* Wv = (const float*)d_in[4];
    float* out = (float*)d_out;

    dim3 gg(NSEG / 128, H_ / 128, 3);
    gemm_qkv<<<gg, 256>>>(x, Wq, Wk, Wv);

    zero_counts_kernel<<<NSEG / 256, 256>>>();
    hist_kernel<<<E_ / 256, 256>>>(ei);
    scan_kernel<<<1, 1024>>>();
    scatter_kernel<<<E_ / 256, 256>>>(ei);

    attn_kernel<<<NSEG / 4, 128>>>(out);
}

// round 3
// speedup vs baseline: 1.6142x; 1.6142x over previous
#include <cuda_runtime.h>
#include <cuda_bf16.h>
#include <cstdint>

#define B_   8
#define N_   1024
#define H_   768
#define NH_  12
#define HD_  64
#define E_   131072
#define NSEG 8192   // B_*N_

// ---------------- device scratch (no allocations allowed) ----------------
__device__ float g_q[NSEG * H_];
__device__ float g_k[NSEG * H_];
__device__ float g_v[NSEG * H_];
__device__ __nv_bfloat16 g_Ahi[NSEG * H_];
__device__ __nv_bfloat16 g_Alo[NSEG * H_];
__device__ __nv_bfloat16 g_Wthi[3 * H_ * H_];   // transposed: [z][n][k]
__device__ __nv_bfloat16 g_Wtlo[3 * H_ * H_];
__device__ int   g_counts[NSEG];
__device__ int   g_offsets[NSEG + 1];
__device__ int   g_cursor[NSEG];
__device__ int   g_rowj[E_];

// ---------------- helpers ----------------
__device__ __forceinline__ uint32_t smem_u32(const void* p) {
    uint32_t a;
    asm("{ .reg .u64 t; cvta.to.shared.u64 t, %1; cvt.u32.u64 %0, t; }" : "=r"(a) : "l"(p));
    return a;
}
__device__ __forceinline__ void cp_async16(uint32_t s, const void* g) {
    asm volatile("cp.async.cg.shared.global [%0], [%1], 16;" :: "r"(s), "l"(g) : "memory");
}
__device__ __forceinline__ void cp_commit() {
    asm volatile("cp.async.commit_group;" ::: "memory");
}
template <int N>
__device__ __forceinline__ void cp_wait() {
    asm volatile("cp.async.wait_group %0;" :: "n"(N) : "memory");
}
__device__ __forceinline__ void ldsm_x4(uint32_t& r0, uint32_t& r1, uint32_t& r2, uint32_t& r3,
                                        uint32_t addr) {
    asm volatile("ldmatrix.sync.aligned.m8n8.x4.shared.b16 {%0,%1,%2,%3}, [%4];"
                 : "=r"(r0), "=r"(r1), "=r"(r2), "=r"(r3) : "r"(addr));
}
__device__ __forceinline__ void ldsm_x2(uint32_t& r0, uint32_t& r1, uint32_t addr) {
    asm volatile("ldmatrix.sync.aligned.m8n8.x2.shared.b16 {%0,%1}, [%2];"
                 : "=r"(r0), "=r"(r1) : "r"(addr));
}
__device__ __forceinline__ void mma_bf16(float* d, const uint32_t* a, const uint32_t* b) {
    asm volatile(
        "mma.sync.aligned.m16n8k16.row.col.f32.bf16.bf16.f32 "
        "{%0,%1,%2,%3}, {%4,%5,%6,%7}, {%8,%9}, {%0,%1,%2,%3};"
        : "+f"(d[0]), "+f"(d[1]), "+f"(d[2]), "+f"(d[3])
        : "r"(a[0]), "r"(a[1]), "r"(a[2]), "r"(a[3]), "r"(b[0]), "r"(b[1]));
}

// swizzled offset within a 128-row x 64B (32 bf16) tile; conflict-free for ldmatrix
__device__ __forceinline__ uint32_t tile_off(int row, int chunk) {
    return (uint32_t)(row * 64 + ((chunk ^ ((row >> 1) & 3)) << 4));
}

// ---------------- precompute: bf16 hi/lo splits ----------------
__global__ void split_A_kernel(const float* __restrict__ x) {
    int i = blockIdx.x * blockDim.x + threadIdx.x;
    if (i < NSEG * H_) {
        float v = x[i];
        __nv_bfloat16 hi = __float2bfloat16(v);
        float lo = v - __bfloat162float(hi);
        g_Ahi[i] = hi;
        g_Alo[i] = __float2bfloat16(lo);
    }
}
// W[k][n] -> Wt[n][k], split
__global__ void split_W_kernel(const float* __restrict__ Wq, const float* __restrict__ Wk,
                               const float* __restrict__ Wv) {
    int i = blockIdx.x * blockDim.x + threadIdx.x;
    if (i >= 3 * H_ * H_) return;
    int z = i / (H_ * H_);
    int r = i - z * (H_ * H_);
    int k = r / H_, n = r - k * H_;
    const float* W = (z == 0) ? Wq : (z == 1) ? Wk : Wv;
    float v = W[(size_t)k * H_ + n];
    __nv_bfloat16 hi = __float2bfloat16(v);
    float lo = v - __bfloat162float(hi);
    size_t o = (size_t)z * H_ * H_ + (size_t)n * H_ + k;
    g_Wthi[o] = hi;
    g_Wtlo[o] = __float2bfloat16(lo);
}

// ---------------- HMMA bf16 GEMM with 3-term split ----------------
// C(z) = A(8192x768) @ W(z)(768x768). CTA tile 128x128, BK=32, double-buffered cp.async.
#define BK_     32
#define NSTAGE_ 24               // 768/32
#define TILE_B  8192             // 128 rows x 64B
#define STG_B   (4 * TILE_B)     // Ahi|Alo|Bhi|Blo
#define OFF_AHI 0
#define OFF_ALO 8192
#define OFF_BHI 16384
#define OFF_BLO 24576

__global__ __launch_bounds__(256, 1)
void gemm_mma_kernel() {
    extern __shared__ char smem[];
    const int tid  = threadIdx.x;
    const int wid  = tid >> 5;
    const int lane = tid & 31;
    const int warp_m = wid & 1;        // 2 warps over M -> 64 rows each
    const int warp_n = wid >> 1;       // 4 warps over N -> 32 cols each

    const int m0 = blockIdx.x * 128;
    const int n0 = blockIdx.y * 128;
    const int z  = blockIdx.z;
    const __nv_bfloat16* Bt_hi = g_Wthi + (size_t)z * H_ * H_;
    const __nv_bfloat16* Bt_lo = g_Wtlo + (size_t)z * H_ * H_;
    float* C = (z == 0) ? g_q : (z == 1) ? g_k : g_v;

    const uint32_t sbase = smem_u32(smem);

    // global load mapping: 512 16B-chunks per tile, 2 per thread
    const int row0 = tid >> 2;            // 0..63
    const int c0   = tid & 3;             // chunk 0..3
    // second chunk: rows 64..127
    float acc[4][4][4];
    #pragma unroll
    for (int i = 0; i < 4; i++)
        #pragma unroll
        for (int j = 0; j < 4; j++)
            #pragma unroll
            for (int r = 0; r < 4; r++) acc[i][j][r] = 0.f;

    auto prefetch = [&](int t) {
        const int k0 = t * BK_;
        const uint32_t stg = sbase + (uint32_t)(t & 1) * STG_B;
        #pragma unroll
        for (int half = 0; half < 2; half++) {
            int row = row0 + half * 64;
            uint32_t so = tile_off(row, c0);
            size_t goA = (size_t)(m0 + row) * H_ + k0 + c0 * 8;
            size_t goB = (size_t)(n0 + row) * H_ + k0 + c0 * 8;
            cp_async16(stg + OFF_AHI + so, g_Ahi + goA);
            cp_async16(stg + OFF_ALO + so, g_Alo + goA);
            cp_async16(stg + OFF_BHI + so, Bt_hi + goB);
            cp_async16(stg + OFF_BLO + so, Bt_lo + goB);
        }
        cp_commit();
    };

    prefetch(0);

    for (int t = 0; t < NSTAGE_; t++) {
        if (t + 1 < NSTAGE_) {
            prefetch(t + 1);
            cp_wait<1>();
        } else {
            cp_wait<0>();
        }
        __syncthreads();

        const uint32_t stg = sbase + (uint32_t)(t & 1) * STG_B;
        #pragma unroll
        for (int ks = 0; ks < 2; ks++) {
            // A fragments (hi & lo), 4 m-tiles of 16 rows
            uint32_t ahi[4][4], alo[4][4];
            {
                int arow = warp_m * 64 + (lane & 15);
                int achk = ks * 2 + (lane >> 4);
                uint32_t so = tile_off(arow, achk);
                #pragma unroll
                for (int mt = 0; mt < 4; mt++) {
                    // +16 rows => +16*64 bytes, same chunk-swizzle class (row>>1 parity preserved)
                    uint32_t a = stg + so + (uint32_t)(mt * 16 * 64);
                    ldsm_x4(ahi[mt][0], ahi[mt][1], ahi[mt][2], ahi[mt][3], a + OFF_AHI);
                    ldsm_x4(alo[mt][0], alo[mt][1], alo[mt][2], alo[mt][3], a + OFF_ALO);
                }
            }
            // B fragments (hi & lo), 4 n-tiles of 8 rows
            uint32_t bhi[4][2], blo[4][2];
            {
                int brow = warp_n * 32 + (lane & 7);
                int bchk = ks * 2 + ((lane >> 3) & 1);
                uint32_t so = tile_off(brow, bchk);
                #pragma unroll
                for (int nt = 0; nt < 4; nt++) {
                    uint32_t a = stg + so + (uint32_t)(nt * 8 * 64);
                    ldsm_x2(bhi[nt][0], bhi[nt][1], a + OFF_BHI);
                    ldsm_x2(blo[nt][0], blo[nt][1], a + OFF_BLO);
                }
            }
            #pragma unroll
            for (int mt = 0; mt < 4; mt++)
                #pragma unroll
                for (int nt = 0; nt < 4; nt++) {
                    mma_bf16(acc[mt][nt], ahi[mt], bhi[nt]);
                    mma_bf16(acc[mt][nt], ahi[mt], blo[nt]);
                    mma_bf16(acc[mt][nt], alo[mt], bhi[nt]);
                }
        }
        __syncthreads();
    }

    // epilogue: warp tile 64x32 at (m0 + warp_m*64, n0 + warp_n*32)
    {
        int rbase = m0 + warp_m * 64 + (lane >> 2);
        int cbase = n0 + warp_n * 32 + (lane & 3) * 2;
        #pragma unroll
        for (int mt = 0; mt < 4; mt++)
            #pragma unroll
            for (int nt = 0; nt < 4; nt++) {
                float* p0 = C + (size_t)(rbase + mt * 16) * H_ + cbase + nt * 8;
                float* p1 = p0 + 8 * H_;
                *(float2*)p0 = make_float2(acc[mt][nt][0], acc[mt][nt][1]);
                *(float2*)p1 = make_float2(acc[mt][nt][2], acc[mt][nt][3]);
            }
    }
}

// ---------------- edge bucketing: counts -> scan -> scatter ----------------
__global__ void zero_counts_kernel() {
    int i = blockIdx.x * blockDim.x + threadIdx.x;
    if (i < NSEG) g_counts[i] = 0;
}

__global__ void hist_kernel(const int* __restrict__ ei) {
    int e = blockIdx.x * blockDim.x + threadIdx.x;
    if (e < E_) {
        int seg = ei[e] * N_ + ei[E_ + e];
        atomicAdd(&g_counts[seg], 1);
    }
}

__global__ __launch_bounds__(1024)
void scan_kernel() {
    __shared__ int sums[1024];
    int tid = threadIdx.x;
    int base = tid * 8;
    int c[8];
    int tot = 0;
    #pragma unroll
    for (int i = 0; i < 8; i++) { c[i] = g_counts[base + i]; tot += c[i]; }
    sums[tid] = tot;
    __syncthreads();
    for (int off = 1; off < 1024; off <<= 1) {
        int v = (tid >= off) ? sums[tid - off] : 0;
        __syncthreads();
        sums[tid] += v;
        __syncthreads();
    }
    int run = sums[tid] - tot;
    #pragma unroll
    for (int i = 0; i < 8; i++) {
        g_offsets[base + i] = run;
        g_cursor[base + i]  = run;
        run += c[i];
    }
    if (tid == 1023) g_offsets[NSEG] = run;
}

__global__ void scatter_kernel(const int* __restrict__ ei) {
    int e = blockIdx.x * blockDim.x + threadIdx.x;
    if (e < E_) {
        int b   = ei[e];
        int seg = b * N_ + ei[E_ + e];
        int pos = atomicAdd(&g_cursor[seg], 1);
        g_rowj[pos] = b * N_ + ei[2 * E_ + e];
    }
}

// ---------------- attention: one warp per segment, online softmax ----------------
__global__ __launch_bounds__(128)
void attn_kernel(float* __restrict__ out) {
    int wglobal = (blockIdx.x * blockDim.x + threadIdx.x) >> 5;
    if (wglobal >= NSEG) return;
    int lane = threadIdx.x & 31;

    const float* qrow = g_q + (size_t)wglobal * H_;
    float qr[24];
    #pragma unroll
    for (int t = 0; t < 24; t++) qr[t] = qrow[lane + 32 * t];

    float m[12], r[12], acc[24];
    #pragma unroll
    for (int h = 0; h < 12; h++) { m[h] = -1e30f; r[h] = 0.f; }
    #pragma unroll
    for (int t = 0; t < 24; t++) acc[t] = 0.f;

    int p0 = g_offsets[wglobal];
    int p1 = g_offsets[wglobal + 1];
    for (int p = p0; p < p1; p++) {
        int rowj = g_rowj[p];
        const float* krow = g_k + (size_t)rowj * H_;
        const float* vrow = g_v + (size_t)rowj * H_;

        float part[12];
        #pragma unroll
        for (int h = 0; h < 12; h++) {
            part[h] = qr[2 * h]     * krow[lane + 64 * h]
                    + qr[2 * h + 1] * krow[lane + 64 * h + 32];
        }
        #pragma unroll
        for (int off = 16; off > 0; off >>= 1)
            #pragma unroll
            for (int h = 0; h < 12; h++)
                part[h] += __shfl_xor_sync(0xffffffffu, part[h], off);

        float vr[24];
        #pragma unroll
        for (int t = 0; t < 24; t++) vr[t] = vrow[lane + 32 * t];

        #pragma unroll
        for (int h = 0; h < 12; h++) {
            float sc = part[h] * 0.125f;
            float mn = fmaxf(m[h], sc);
            float f  = __expf(m[h] - mn);
            float w  = __expf(sc - mn);
            r[h] = r[h] * f + w;
            m[h] = mn;
            acc[2 * h]     = acc[2 * h]     * f + w * vr[2 * h];
            acc[2 * h + 1] = acc[2 * h + 1] * f + w * vr[2 * h + 1];
        }
    }

    float inv[12];
    #pragma unroll
    for (int h = 0; h < 12; h++) inv[h] = 1.f / fmaxf(r[h], 1e-9f);
    float* orow = out + (size_t)wglobal * H_;
    #pragma unroll
    for (int t = 0; t < 24; t++) orow[lane + 32 * t] = acc[t] * inv[t >> 1];
}

// ---------------- launch ----------------
extern "C" void kernel_launch(void* const* d_in, const int* in_sizes, int n_in,
                              void* d_out, int out_size) {
    const float* x  = (const float*)d_in[0];
    const int*   ei = (const int*)  d_in[1];
    const float* Wq = (const float*)d_in[2];
    const float* Wk = (const float*)d_in[3];
    const float* Wv = (const float*)d_in[4];
    float* out = (float*)d_out;

    cudaFuncSetAttribute(gemm_mma_kernel, cudaFuncAttributeMaxDynamicSharedMemorySize,
                         2 * STG_B);

    split_A_kernel<<<(NSEG * H_ + 255) / 256, 256>>>(x);
    split_W_kernel<<<(3 * H_ * H_ + 255) / 256, 256>>>(Wq, Wk, Wv);

    dim3 gg(NSEG / 128, H_ / 128, 3);
    gemm_mma_kernel<<<gg, 256, 2 * STG_B>>>();

    zero_counts_kernel<<<NSEG / 256, 256>>>();
    hist_kernel<<<E_ / 256, 256>>>(ei);
    scan_kernel<<<1, 1024>>>();
    scatter_kernel<<<E_ / 256, 256>>>(ei);

    attn_kernel<<<NSEG / 4, 128>>>(out);
}

// round 4
// speedup vs baseline: 2.3372x; 1.4479x over previous
#include <cuda_runtime.h>
#include <cuda_bf16.h>
#include <cstdint>

#define B_   8
#define N_   1024
#define H_   768
#define NH_  12
#define HD_  64
#define E_   131072
#define NSEG 8192   // B_*N_

// ---------------- device scratch (no allocations allowed) ----------------
__device__ float g_q[NSEG * H_];
__device__ float g_k[NSEG * H_];
__device__ float g_v[NSEG * H_];
__device__ __nv_bfloat16 g_Ahi[NSEG * H_];
__device__ __nv_bfloat16 g_Alo[NSEG * H_];
__device__ __nv_bfloat16 g_Wthi[3 * H_ * H_];   // transposed: [z][n][k]
__device__ __nv_bfloat16 g_Wtlo[3 * H_ * H_];
__device__ int   g_counts[NSEG];
__device__ int   g_offsets[NSEG + 1];
__device__ int   g_cursor[NSEG];
__device__ int   g_rowj[E_];

// ---------------- helpers ----------------
__device__ __forceinline__ uint32_t smem_u32(const void* p) {
    uint32_t a;
    asm("{ .reg .u64 t; cvta.to.shared.u64 t, %1; cvt.u32.u64 %0, t; }" : "=r"(a) : "l"(p));
    return a;
}
__device__ __forceinline__ void cp_async16(uint32_t s, const void* g) {
    asm volatile("cp.async.cg.shared.global [%0], [%1], 16;" :: "r"(s), "l"(g) : "memory");
}
__device__ __forceinline__ void cp_commit() {
    asm volatile("cp.async.commit_group;" ::: "memory");
}
template <int N>
__device__ __forceinline__ void cp_wait() {
    asm volatile("cp.async.wait_group %0;" :: "n"(N) : "memory");
}
__device__ __forceinline__ void ldsm_x4(uint32_t& r0, uint32_t& r1, uint32_t& r2, uint32_t& r3,
                                        uint32_t addr) {
    asm volatile("ldmatrix.sync.aligned.m8n8.x4.shared.b16 {%0,%1,%2,%3}, [%4];"
                 : "=r"(r0), "=r"(r1), "=r"(r2), "=r"(r3) : "r"(addr));
}
__device__ __forceinline__ void ldsm_x2(uint32_t& r0, uint32_t& r1, uint32_t addr) {
    asm volatile("ldmatrix.sync.aligned.m8n8.x2.shared.b16 {%0,%1}, [%2];"
                 : "=r"(r0), "=r"(r1) : "r"(addr));
}
__device__ __forceinline__ void mma_bf16(float* d, const uint32_t* a, const uint32_t* b) {
    asm volatile(
        "mma.sync.aligned.m16n8k16.row.col.f32.bf16.bf16.f32 "
        "{%0,%1,%2,%3}, {%4,%5,%6,%7}, {%8,%9}, {%0,%1,%2,%3};"
        : "+f"(d[0]), "+f"(d[1]), "+f"(d[2]), "+f"(d[3])
        : "r"(a[0]), "r"(a[1]), "r"(a[2]), "r"(a[3]), "r"(b[0]), "r"(b[1]));
}
__device__ __forceinline__ float ex2f(float x) {
    float y;
    asm("ex2.approx.ftz.f32 %0, %1;" : "=f"(y) : "f"(x));
    return y;
}

// swizzled offset within a 128-row x 64B (32 bf16) tile; conflict-free for ldmatrix
__device__ __forceinline__ uint32_t tile_off(int row, int chunk) {
    return (uint32_t)(row * 64 + ((chunk ^ ((row >> 1) & 3)) << 4));
}

// ---------------- precompute: bf16 hi/lo splits (vectorized) ----------------
__global__ void split_A_kernel(const float* __restrict__ x) {
    int i = blockIdx.x * blockDim.x + threadIdx.x;   // float4 index
    if (i < NSEG * H_ / 4) {
        float4 v = ((const float4*)x)[i];
        __nv_bfloat16 h0 = __float2bfloat16(v.x), h1 = __float2bfloat16(v.y);
        __nv_bfloat16 h2 = __float2bfloat16(v.z), h3 = __float2bfloat16(v.w);
        __nv_bfloat162* hp = (__nv_bfloat162*)g_Ahi;
        __nv_bfloat162* lp = (__nv_bfloat162*)g_Alo;
        hp[2 * i]     = __nv_bfloat162(h0, h1);
        hp[2 * i + 1] = __nv_bfloat162(h2, h3);
        lp[2 * i]     = __nv_bfloat162(__float2bfloat16(v.x - __bfloat162float(h0)),
                                       __float2bfloat16(v.y - __bfloat162float(h1)));
        lp[2 * i + 1] = __nv_bfloat162(__float2bfloat16(v.z - __bfloat162float(h2)),
                                       __float2bfloat16(v.w - __bfloat162float(h3)));
    }
}
// W[k][n] -> Wt[n][k], split; also zero counts
__global__ void split_W_kernel(const float* __restrict__ Wq, const float* __restrict__ Wk,
                               const float* __restrict__ Wv) {
    int i = blockIdx.x * blockDim.x + threadIdx.x;
    if (i < NSEG) g_counts[i] = 0;
    if (i >= 3 * H_ * H_) return;
    int z = i / (H_ * H_);
    int r = i - z * (H_ * H_);
    int k = r / H_, n = r - k * H_;
    const float* W = (z == 0) ? Wq : (z == 1) ? Wk : Wv;
    float v = W[(size_t)k * H_ + n];
    __nv_bfloat16 hi = __float2bfloat16(v);
    float lo = v - __bfloat162float(hi);
    size_t o = (size_t)z * H_ * H_ + (size_t)n * H_ + k;
    g_Wthi[o] = hi;
    g_Wtlo[o] = __float2bfloat16(lo);
}

// ---------------- HMMA bf16 GEMM with 3-term split ----------------
// C(z) = A(8192x768) @ W(z)(768x768). CTA tile 128x128, BK=32, double-buffered cp.async.
#define BK_     32
#define NSTAGE_ 24               // 768/32
#define TILE_B  8192             // 128 rows x 64B
#define STG_B   (4 * TILE_B)     // Ahi|Alo|Bhi|Blo
#define OFF_AHI 0
#define OFF_ALO 8192
#define OFF_BHI 16384
#define OFF_BLO 24576

__global__ __launch_bounds__(256, 1)
void gemm_mma_kernel() {
    extern __shared__ char smem[];
    const int tid  = threadIdx.x;
    const int wid  = tid >> 5;
    const int lane = tid & 31;
    const int warp_m = wid & 1;        // 2 warps over M -> 64 rows each
    const int warp_n = wid >> 1;       // 4 warps over N -> 32 cols each

    const int m0 = blockIdx.x * 128;
    const int n0 = blockIdx.y * 128;
    const int z  = blockIdx.z;
    const __nv_bfloat16* Bt_hi = g_Wthi + (size_t)z * H_ * H_;
    const __nv_bfloat16* Bt_lo = g_Wtlo + (size_t)z * H_ * H_;
    float* C = (z == 0) ? g_q : (z == 1) ? g_k : g_v;

    const uint32_t sbase = smem_u32(smem);

    const int row0 = tid >> 2;            // 0..63
    const int c0   = tid & 3;             // chunk 0..3
    float acc[4][4][4];
    #pragma unroll
    for (int i = 0; i < 4; i++)
        #pragma unroll
        for (int j = 0; j < 4; j++)
            #pragma unroll
            for (int r = 0; r < 4; r++) acc[i][j][r] = 0.f;

    auto prefetch = [&](int t) {
        const int k0 = t * BK_;
        const uint32_t stg = sbase + (uint32_t)(t & 1) * STG_B;
        #pragma unroll
        for (int half = 0; half < 2; half++) {
            int row = row0 + half * 64;
            uint32_t so = tile_off(row, c0);
            size_t goA = (size_t)(m0 + row) * H_ + k0 + c0 * 8;
            size_t goB = (size_t)(n0 + row) * H_ + k0 + c0 * 8;
            cp_async16(stg + OFF_AHI + so, g_Ahi + goA);
            cp_async16(stg + OFF_ALO + so, g_Alo + goA);
            cp_async16(stg + OFF_BHI + so, Bt_hi + goB);
            cp_async16(stg + OFF_BLO + so, Bt_lo + goB);
        }
        cp_commit();
    };

    prefetch(0);

    for (int t = 0; t < NSTAGE_; t++) {
        if (t + 1 < NSTAGE_) {
            prefetch(t + 1);
            cp_wait<1>();
        } else {
            cp_wait<0>();
        }
        __syncthreads();

        const uint32_t stg = sbase + (uint32_t)(t & 1) * STG_B;
        #pragma unroll
        for (int ks = 0; ks < 2; ks++) {
            uint32_t ahi[4][4], alo[4][4];
            {
                int arow = warp_m * 64 + (lane & 15);
                int achk = ks * 2 + (lane >> 4);
                uint32_t so = tile_off(arow, achk);
                #pragma unroll
                for (int mt = 0; mt < 4; mt++) {
                    uint32_t a = stg + so + (uint32_t)(mt * 16 * 64);
                    ldsm_x4(ahi[mt][0], ahi[mt][1], ahi[mt][2], ahi[mt][3], a + OFF_AHI);
                    ldsm_x4(alo[mt][0], alo[mt][1], alo[mt][2], alo[mt][3], a + OFF_ALO);
                }
            }
            uint32_t bhi[4][2], blo[4][2];
            {
                int brow = warp_n * 32 + (lane & 7);
                int bchk = ks * 2 + ((lane >> 3) & 1);
                uint32_t so = tile_off(brow, bchk);
                #pragma unroll
                for (int nt = 0; nt < 4; nt++) {
                    uint32_t a = stg + so + (uint32_t)(nt * 8 * 64);
                    ldsm_x2(bhi[nt][0], bhi[nt][1], a + OFF_BHI);
                    ldsm_x2(blo[nt][0], blo[nt][1], a + OFF_BLO);
                }
            }
            #pragma unroll
            for (int mt = 0; mt < 4; mt++)
                #pragma unroll
                for (int nt = 0; nt < 4; nt++) {
                    mma_bf16(acc[mt][nt], ahi[mt], bhi[nt]);
                    mma_bf16(acc[mt][nt], ahi[mt], blo[nt]);
                    mma_bf16(acc[mt][nt], alo[mt], bhi[nt]);
                }
        }
        __syncthreads();
    }

    {
        int rbase = m0 + warp_m * 64 + (lane >> 2);
        int cbase = n0 + warp_n * 32 + (lane & 3) * 2;
        #pragma unroll
        for (int mt = 0; mt < 4; mt++)
            #pragma unroll
            for (int nt = 0; nt < 4; nt++) {
                float* p0 = C + (size_t)(rbase + mt * 16) * H_ + cbase + nt * 8;
                float* p1 = p0 + 8 * H_;
                *(float2*)p0 = make_float2(acc[mt][nt][0], acc[mt][nt][1]);
                *(float2*)p1 = make_float2(acc[mt][nt][2], acc[mt][nt][3]);
            }
    }
}

// ---------------- edge bucketing ----------------
__global__ void hist_kernel(const int* __restrict__ ei) {
    int e = blockIdx.x * blockDim.x + threadIdx.x;
    if (e < E_) {
        int seg = ei[e] * N_ + ei[E_ + e];
        atomicAdd(&g_counts[seg], 1);
    }
}

__global__ __launch_bounds__(1024)
void scan_kernel() {
    __shared__ int sums[1024];
    int tid = threadIdx.x;
    int base = tid * 8;
    int c[8];
    int tot = 0;
    #pragma unroll
    for (int i = 0; i < 8; i++) { c[i] = g_counts[base + i]; tot += c[i]; }
    sums[tid] = tot;
    __syncthreads();
    for (int off = 1; off < 1024; off <<= 1) {
        int v = (tid >= off) ? sums[tid - off] : 0;
        __syncthreads();
        sums[tid] += v;
        __syncthreads();
    }
    int run = sums[tid] - tot;
    #pragma unroll
    for (int i = 0; i < 8; i++) {
        g_offsets[base + i] = run;
        g_cursor[base + i]  = run;
        run += c[i];
    }
    if (tid == 1023) g_offsets[NSEG] = run;
}

__global__ void scatter_kernel(const int* __restrict__ ei) {
    int e = blockIdx.x * blockDim.x + threadIdx.x;
    if (e < E_) {
        int b   = ei[e];
        int seg = b * N_ + ei[E_ + e];
        int pos = atomicAdd(&g_cursor[seg], 1);
        g_rowj[pos] = b * N_ + ei[2 * E_ + e];
    }
}

// ---------------- attention: one warp per segment, float4 lanes own heads ----------------
// chunk c (of 6) covers elements [128c, 128c+128). lane l holds elems 128c+4l..+3.
// head(c, l) = 2c + (l>=16). Reduce dots within 16-lane halves (shfl_xor 8,4,2,1).
#define L2E 1.44269504f
__global__ __launch_bounds__(256)
void attn_kernel(float* __restrict__ out) {
    int wglobal = (blockIdx.x * blockDim.x + threadIdx.x) >> 5;
    if (wglobal >= NSEG) return;
    int lane = threadIdx.x & 31;

    const float4* qrow = (const float4*)(g_q + (size_t)wglobal * H_);
    float4 qf[6];
    #pragma unroll
    for (int c = 0; c < 6; c++) qf[c] = qrow[c * 32 + lane];

    float m[6], r[6];
    float4 acc[6];
    #pragma unroll
    for (int c = 0; c < 6; c++) {
        m[c] = -1e30f; r[c] = 0.f;
        acc[c] = make_float4(0.f, 0.f, 0.f, 0.f);
    }

    int p0 = g_offsets[wglobal];
    int p1 = g_offsets[wglobal + 1];
    for (int p = p0; p < p1; p++) {
        int rowj = g_rowj[p];
        const float4* kr = (const float4*)(g_k + (size_t)rowj * H_);
        const float4* vr = (const float4*)(g_v + (size_t)rowj * H_);

        float part[6];
        #pragma unroll
        for (int c = 0; c < 6; c++) {
            float4 kf = kr[c * 32 + lane];
            part[c] = qf[c].x * kf.x + qf[c].y * kf.y + qf[c].z * kf.z + qf[c].w * kf.w;
        }
        float4 vf[6];
        #pragma unroll
        for (int c = 0; c < 6; c++) vf[c] = vr[c * 32 + lane];

        #pragma unroll
        for (int off = 8; off > 0; off >>= 1)
            #pragma unroll
            for (int c = 0; c < 6; c++)
                part[c] += __shfl_xor_sync(0xffffffffu, part[c], off);

        #pragma unroll
        for (int c = 0; c < 6; c++) {
            float s2 = part[c] * (0.125f * L2E);   // score in log2 domain
            float mn = fmaxf(m[c], s2);
            float f  = ex2f(m[c] - mn);
            float w  = ex2f(s2 - mn);
            r[c] = r[c] * f + w;
            m[c] = mn;
            acc[c].x = acc[c].x * f + w * vf[c].x;
            acc[c].y = acc[c].y * f + w * vf[c].y;
            acc[c].z = acc[c].z * f + w * vf[c].z;
            acc[c].w = acc[c].w * f + w * vf[c].w;
        }
    }

    float4* orow = (float4*)(out + (size_t)wglobal * H_);
    #pragma unroll
    for (int c = 0; c < 6; c++) {
        float inv = 1.f / fmaxf(r[c], 1e-9f);
        orow[c * 32 + lane] = make_float4(acc[c].x * inv, acc[c].y * inv,
                                          acc[c].z * inv, acc[c].w * inv);
    }
}

// ---------------- launch ----------------
extern "C" void kernel_launch(void* const* d_in, const int* in_sizes, int n_in,
                              void* d_out, int out_size) {
    const float* x  = (const float*)d_in[0];
    const int*   ei = (const int*)  d_in[1];
    const float* Wq = (const float*)d_in[2];
    const float* Wk = (const float*)d_in[3];
    const float* Wv = (const float*)d_in[4];
    float* out = (float*)d_out;

    cudaFuncSetAttribute(gemm_mma_kernel, cudaFuncAttributeMaxDynamicSharedMemorySize,
                         2 * STG_B);

    split_A_kernel<<<(NSEG * H_ / 4 + 255) / 256, 256>>>(x);
    split_W_kernel<<<(3 * H_ * H_ + 255) / 256, 256>>>(Wq, Wk, Wv);

    dim3 gg(NSEG / 128, H_ / 128, 3);
    gemm_mma_kernel<<<gg, 256, 2 * STG_B>>>();

    hist_kernel<<<E_ / 256, 256>>>(ei);
    scan_kernel<<<1, 1024>>>();
    scatter_kernel<<<E_ / 256, 256>>>(ei);

    attn_kernel<<<NSEG / 8, 256>>>(out);
}